// round 16
// baseline (speedup 1.0000x reference)
#include <cuda_runtime.h>
#include <cstdint>

// ---------------------------------------------------------------------------
// MultiHeadedEMA == causal + anti-causal first-order EMA per (head, channel).
//   fwd: u[t] = q*u[t-1] + x[t] ;  rev: u[t] = q*u[t+1] + x[t]
//   out[b,l,d] = sum_h wf[h,d]*uf + wr[h,d]*ur,  w = expansion*reduction*a
// Round-16: single fused kernel combining every win from rounds 8-15:
//   - weighted local scans WITH batched register x loads (kernel-A structure)
//   - scan end states double as the chunk aggregates (no separate agg pass)
//   - one grid barrier (512 blocks, 4/SM co-resident: deadlock-free)
//   - post-barrier: windowed lookback (qc=q^32 -> W~1-2) + geometric
//     correction chains + single streaming store. No x / weight loads
//     after the barrier.
// ---------------------------------------------------------------------------

constexpr int kB = 2;
constexpr int kL = 2048;
constexpr int kD = 1024;
constexpr int kH = 8;

constexpr int kChunk   = 32;
constexpr int kNChunk  = kL / kChunk;             // 64
constexpr int kCols    = 256;                     // d-columns per block
constexpr int kThreads = 128;                     // 2 cols/thread -> f32x2
constexpr int kDTiles  = kD / kCols;              // 4
constexpr int kBlocks  = kB * kNChunk * kDTiles;  // 512
constexpr int kRowU64  = kD / 2;                  // 512

// Per-chunk end states (fwd / rev), L2-resident scratch (8 MB).
__device__ __align__(16) float g_sf[kB][kNChunk][kH][kD];
__device__ __align__(16) float g_sr[kB][kNChunk][kH][kD];

// Grid-barrier counter (monotonic; each launch adds exactly kBlocks).
__device__ unsigned g_bar;

using u64 = unsigned long long;

__device__ __forceinline__ u64 pack2(float lo, float hi) {
    u64 r;
    asm("mov.b64 %0, {%1, %2};"
        : "=l"(r) : "r"(__float_as_uint(lo)), "r"(__float_as_uint(hi)));
    return r;
}
__device__ __forceinline__ u64 fma2(u64 a, u64 b, u64 c) {
    u64 r;
    asm("fma.rn.f32x2 %0, %1, %2, %3;" : "=l"(r) : "l"(a), "l"(b), "l"(c));
    return r;
}
__device__ __forceinline__ u64 mul2(u64 a, u64 b) {
    u64 r;
    asm("mul.rn.f32x2 %0, %1, %2;" : "=l"(r) : "l"(a), "l"(b));
    return r;
}
__device__ __forceinline__ u64 add2(u64 a, u64 b) {
    u64 r;
    asm("add.rn.f32x2 %0, %1, %2;" : "=l"(r) : "l"(a), "l"(b));
    return r;
}
__device__ __forceinline__ void store_cs(u64* p, u64 v) {
    float2 f;
    f.x = __uint_as_float((unsigned)(v & 0xffffffffull));
    f.y = __uint_as_float((unsigned)(v >> 32));
    __stcs(reinterpret_cast<float2*>(p), f);
}

// fp32 sigmoid; use sigp(-v) for the (1 - sigmoid(v)) term (no cancellation).
__device__ __forceinline__ float sigp(float v) { return 1.0f / (1.0f + expf(-v)); }

// ---------------------------------------------------------------------------
__global__ void __launch_bounds__(kThreads, 4)
ema_fused(const float* __restrict__ x,
          const float* __restrict__ ex,  const float* __restrict__ re,
          const float* __restrict__ al,  const float* __restrict__ da,
          const float* __restrict__ ral, const float* __restrict__ rda,
          float* __restrict__ out)
{
    __shared__ u64 acc[kChunk * kThreads];           // 32 KB weighted partials
    __shared__ float s_q[2][kH], s_a[2][kH], s_qc[2][kH];
    __shared__ int s_W[2];

    const int tid = threadIdx.x;
    const int blk = blockIdx.x;
    const int dt = blk & (kDTiles - 1);
    const int c  = (blk >> 2) & (kNChunk - 1);
    const int b  = blk >> 8;

    const u64* xs = reinterpret_cast<const u64*>(
        x + ((size_t)b * kL + (size_t)c * kChunk) * kD + dt * kCols) + tid;
    const int d = dt * kCols + 2 * tid;

    // ---- per-head constants -------------------------------------------------
    if (tid < 2 * kH) {
        const int dr = tid >= kH;
        const int h  = tid & (kH - 1);
        const float av = dr ? ral[h] : al[h];
        const float dv = dr ? rda[h] : da[h];
        s_a[dr][h] = sigp(av);
        float q = sigp(-av) * sigp(dv);
        s_q[dr][h] = q;
        float qc = q;
#pragma unroll
        for (int k = 0; k < 5; ++k) qc *= qc;        // q^32
        s_qc[dr][h] = qc;
    }
    __syncthreads();
    if (tid < 2) {
        float m = 0.0f;
#pragma unroll
        for (int h = 0; h < kH; ++h) m = fmaxf(m, s_qc[tid][h]);
        // W = ceil(ln(1e-8)/ln(qcmax)), clamped to full history.
        int W = kNChunk;
        if (m <= 0.0f) W = 0;
        else {
            float lq = logf(m);
            if (lq < -1e-20f) {
                float w = ceilf(-18.4207f / lq);
                W = (w >= (float)kNChunk) ? kNChunk : (int)w;
            }
        }
        s_W[tid] = W;
    }
    __syncthreads();

    // ---- weights (u64 float2 loads), kept in registers throughout ----------
    const u64* exu = reinterpret_cast<const u64*>(ex) + (d >> 1);
    const u64* reu = reinterpret_cast<const u64*>(re) + (d >> 1);
    u64 qF[kH], qR[kH], wF[kH], wR[kH];
#pragma unroll
    for (int h = 0; h < kH; ++h) {
        qF[h] = pack2(s_q[0][h], s_q[0][h]);
        qR[h] = pack2(s_q[1][h], s_q[1][h]);
        float aF = s_a[0][h], aR = s_a[1][h];
        wF[h] = mul2(mul2(exu[h * kRowU64], reu[h * kRowU64]),
                     pack2(aF, aF));
        wR[h] = mul2(mul2(exu[(kH + h) * kRowU64], reu[(kH + h) * kRowU64]),
                     pack2(aR, aR));
    }

    // ---- weighted local FWD scan (8-wide batched x loads) -------------------
    // End state uF[h] == fwd chunk aggregate (published; no separate pass).
    {
        u64 u[kH];
#pragma unroll
        for (int h = 0; h < kH; ++h) u[h] = 0ull;
#pragma unroll
        for (int g = 0; g < kChunk / 8; ++g) {
            u64 xv[8];
#pragma unroll
            for (int j = 0; j < 8; ++j) xv[j] = xs[(g * 8 + j) * kRowU64];
#pragma unroll
            for (int j = 0; j < 8; ++j) {
                u64 fs = 0ull;
#pragma unroll
                for (int h = 0; h < kH; ++h) {
                    u[h] = fma2(qF[h], u[h], xv[j]);
                    fs   = fma2(wF[h], u[h], fs);
                }
                acc[(g * 8 + j) * kThreads + tid] = fs;
            }
        }
#pragma unroll
        for (int h = 0; h < kH; ++h)
            *reinterpret_cast<u64*>(&g_sf[b][c][h][d]) = u[h];
    }

    // ---- weighted local REV scan (x re-read, L1-hot, batched) --------------
    {
        u64 u[kH];
#pragma unroll
        for (int h = 0; h < kH; ++h) u[h] = 0ull;
#pragma unroll
        for (int g = kChunk / 8 - 1; g >= 0; --g) {
            u64 xv[8];
#pragma unroll
            for (int j = 0; j < 8; ++j) xv[j] = xs[(g * 8 + j) * kRowU64];
#pragma unroll
            for (int j = 7; j >= 0; --j) {
                u64 rs = 0ull;
#pragma unroll
                for (int h = 0; h < kH; ++h) {
                    u[h] = fma2(qR[h], u[h], xv[j]);
                    rs   = fma2(wR[h], u[h], rs);
                }
                const int i = g * 8 + j;
                acc[i * kThreads + tid] = add2(acc[i * kThreads + tid], rs);
            }
        }
#pragma unroll
        for (int h = 0; h < kH; ++h)
            *reinterpret_cast<u64*>(&g_sr[b][c][h][d]) = u[h];
    }

    // ---- grid barrier (single) ----------------------------------------------
    __threadfence();
    __syncthreads();
    if (tid == 0) {
        unsigned t = atomicAdd(&g_bar, 1u);
        unsigned target = t - (t % kBlocks) + kBlocks;
        volatile unsigned* p = &g_bar;
        while ((int)(*p - target) < 0) { }
    }
    __syncthreads();

    // ---- lookback prefixes Pf / Pr (qc = q^32 -> W tiny) --------------------
    const int dh = d >> 1;
    const u64* bsf = reinterpret_cast<const u64*>(g_sf) +
                     (size_t)b * kNChunk * kH * kRowU64 + dh;
    const u64* bsr = reinterpret_cast<const u64*>(g_sr) +
                     (size_t)b * kNChunk * kH * kRowU64 + dh;

    u64 Pf[kH], Pr[kH];
    {
        const int Wf = min(s_W[0], c);
        float wk[kH];
#pragma unroll
        for (int h = 0; h < kH; ++h) { Pf[h] = 0ull; wk[h] = 1.0f; }
        for (int k = 0; k < Wf; ++k) {
            const u64* row = bsf + (size_t)(c - 1 - k) * kH * kRowU64;
#pragma unroll
            for (int h = 0; h < kH; ++h) {
                Pf[h] = fma2(pack2(wk[h], wk[h]), row[h * kRowU64], Pf[h]);
                wk[h] *= s_qc[0][h];
            }
        }
        const int Wr = min(s_W[1], kNChunk - 1 - c);
#pragma unroll
        for (int h = 0; h < kH; ++h) { Pr[h] = 0ull; wk[h] = 1.0f; }
        for (int k = 0; k < Wr; ++k) {
            const u64* row = bsr + (size_t)(c + 1 + k) * kH * kRowU64;
#pragma unroll
            for (int h = 0; h < kH; ++h) {
                Pr[h] = fma2(pack2(wk[h], wk[h]), row[h * kRowU64], Pr[h]);
                wk[h] *= s_qc[1][h];
            }
        }
    }

    u64* od = reinterpret_cast<u64*>(
        out + ((size_t)b * kL + (size_t)c * kChunk) * kD + dt * kCols) + tid;

    // ---- fwd correction: acc[i] += sum_h wF*qF^{i+1}*Pf (ascending) --------
    {
        u64 t[kH];
#pragma unroll
        for (int h = 0; h < kH; ++h)
            t[h] = mul2(qF[h], mul2(wF[h], Pf[h]));   // i = 0 term
#pragma unroll
        for (int i = 0; i < kChunk; ++i) {
            u64 cf = t[0];
#pragma unroll
            for (int h = 1; h < kH; ++h) cf = add2(cf, t[h]);
            acc[i * kThreads + tid] = add2(acc[i * kThreads + tid], cf);
#pragma unroll
            for (int h = 0; h < kH; ++h) t[h] = mul2(qF[h], t[h]);
        }
    }
    // ---- rev correction + store: out[i] = acc[i] + sum_h wR*qR^{32-i}*Pr ---
    {
        u64 t[kH];
#pragma unroll
        for (int h = 0; h < kH; ++h)
            t[h] = mul2(qR[h], mul2(wR[h], Pr[h]));   // i = 31 term
#pragma unroll
        for (int i = kChunk - 1; i >= 0; --i) {
            u64 cr = t[0];
#pragma unroll
            for (int h = 1; h < kH; ++h) cr = add2(cr, t[h]);
            store_cs(od + i * kRowU64,
                     add2(acc[i * kThreads + tid], cr));  // out written once
#pragma unroll
            for (int h = 0; h < kH; ++h) t[h] = mul2(qR[h], t[h]);
        }
    }
}

// ---------------------------------------------------------------------------
extern "C" void kernel_launch(void* const* d_in, const int* in_sizes, int n_in,
                              void* d_out, int out_size)
{
    const float* x   = (const float*)d_in[0];
    const float* ex  = (const float*)d_in[1];
    const float* re  = (const float*)d_in[2];
    const float* al  = (const float*)d_in[3];
    const float* da  = (const float*)d_in[4];
    const float* ral = (const float*)d_in[5];
    const float* rda = (const float*)d_in[6];
    float* out = (float*)d_out;

    ema_fused<<<kBlocks, kThreads>>>(x, ex, re, al, da, ral, rda, out);
}

// round 17
// speedup vs baseline: 1.5431x; 1.5431x over previous
#include <cuda_runtime.h>
#include <cstdint>

// ---------------------------------------------------------------------------
// MultiHeadedEMA == causal + anti-causal first-order EMA per (head, channel).
//   fwd: u[t] = q*u[t-1] + x[t] ;  rev: u[t] = q*u[t+1] + x[t]
//   out[b,l,d] = sum_h wf[h,d]*uf + wr[h,d]*ur,  w = expansion*reduction*a
// Round-17 = round-9 structure (best: 19.17us) + convoy-aware deltas:
//   - aggregates published ASAP (cheap unweighted scans first)
//   - EARLY barrier arrive, then weight prefetch/compute in the barrier
//     shadow, then spin (weight cold-DRAM latency hidden under other
//     blocks' phase-1)
//   - heavy weighted rescans stay post-barrier, x L1-hot, out stored once.
// ---------------------------------------------------------------------------

constexpr int kB = 2;
constexpr int kL = 2048;
constexpr int kD = 1024;
constexpr int kH = 8;

constexpr int kChunk   = 32;
constexpr int kNChunk  = kL / kChunk;             // 64
constexpr int kCols    = 256;                     // d-columns per block
constexpr int kThreads = 128;                     // 2 cols/thread -> f32x2
constexpr int kDTiles  = kD / kCols;              // 4
constexpr int kBlocks  = kB * kNChunk * kDTiles;  // 512 (<= 592 slots @4/SM)
constexpr int kRowU64  = kD / 2;                  // 512

// Per-chunk end states (fwd / rev), L2-resident scratch (8 MB).
__device__ __align__(16) float g_sf[kB][kNChunk][kH][kD];
__device__ __align__(16) float g_sr[kB][kNChunk][kH][kD];

// Grid-barrier counter (monotonic; each launch adds exactly kBlocks).
__device__ unsigned g_bar;

using u64 = unsigned long long;

__device__ __forceinline__ u64 pack2(float lo, float hi) {
    u64 r;
    asm("mov.b64 %0, {%1, %2};"
        : "=l"(r) : "r"(__float_as_uint(lo)), "r"(__float_as_uint(hi)));
    return r;
}
__device__ __forceinline__ u64 fma2(u64 a, u64 b, u64 c) {
    u64 r;
    asm("fma.rn.f32x2 %0, %1, %2, %3;" : "=l"(r) : "l"(a), "l"(b), "l"(c));
    return r;
}
__device__ __forceinline__ u64 mul2(u64 a, u64 b) {
    u64 r;
    asm("mul.rn.f32x2 %0, %1, %2;" : "=l"(r) : "l"(a), "l"(b));
    return r;
}
__device__ __forceinline__ u64 add2(u64 a, u64 b) {
    u64 r;
    asm("add.rn.f32x2 %0, %1, %2;" : "=l"(r) : "l"(a), "l"(b));
    return r;
}
__device__ __forceinline__ void store_cs(u64* p, u64 v) {
    float2 f;
    f.x = __uint_as_float((unsigned)(v & 0xffffffffull));
    f.y = __uint_as_float((unsigned)(v >> 32));
    __stcs(reinterpret_cast<float2*>(p), f);
}

// fp32 sigmoid; use sigp(-v) for the (1 - sigmoid(v)) term (no cancellation).
__device__ __forceinline__ float sigp(float v) { return 1.0f / (1.0f + expf(-v)); }

// ---------------------------------------------------------------------------
__global__ void __launch_bounds__(kThreads, 4)
ema_fused(const float* __restrict__ x,
          const float* __restrict__ ex,  const float* __restrict__ re,
          const float* __restrict__ al,  const float* __restrict__ da,
          const float* __restrict__ ral, const float* __restrict__ rda,
          float* __restrict__ out)
{
    __shared__ u64 acc[kChunk * kThreads];           // 32 KB fwd partials
    __shared__ float s_q[2][kH], s_a[2][kH], s_qc[2][kH];
    __shared__ int s_W[2];
    __shared__ unsigned s_tgt;

    const int tid = threadIdx.x;
    const int blk = blockIdx.x;
    const int dt = blk & (kDTiles - 1);
    const int c  = (blk >> 2) & (kNChunk - 1);
    const int b  = blk >> 8;

    // ---- per-head constants -------------------------------------------------
    if (tid < 2 * kH) {
        const int dr = tid >= kH;
        const int h  = tid & (kH - 1);
        const float av = dr ? ral[h] : al[h];
        const float dv = dr ? rda[h] : da[h];
        s_a[dr][h] = sigp(av);
        float q = sigp(-av) * sigp(dv);
        s_q[dr][h] = q;
        float qc = q;
#pragma unroll
        for (int k = 0; k < 5; ++k) qc *= qc;        // q^32
        s_qc[dr][h] = qc;
    }
    __syncthreads();
    if (tid < 2) {
        float m = 0.0f;
#pragma unroll
        for (int h = 0; h < kH; ++h) m = fmaxf(m, s_qc[tid][h]);
        // W = ceil(ln(1e-8)/ln(qcmax)), clamped to full history.
        int W = kNChunk;
        if (m <= 0.0f) W = 0;
        else {
            float lq = logf(m);
            if (lq < -1e-20f) {
                float w = ceilf(-18.4207f / lq);
                W = (w >= (float)kNChunk) ? kNChunk : (int)w;
            }
        }
        s_W[tid] = W;    // read only after the grid barrier (ordered by it)
    }

    const u64* xs = reinterpret_cast<const u64*>(
        x + ((size_t)b * kL + (size_t)c * kChunk) * kD + dt * kCols) + tid;
    const int d = dt * kCols + 2 * tid;

    // ================= phase 1: cheap unweighted scans, publish ASAP ========
    {
        u64 q2[kH], s[kH];
#pragma unroll
        for (int h = 0; h < kH; ++h) {
            float q = s_q[0][h];
            q2[h] = pack2(q, q);
            s[h] = 0ull;
        }
#pragma unroll
        for (int i = 0; i < kChunk; ++i) {
            u64 xv = xs[i * kRowU64];                // DRAM read, warms L1
#pragma unroll
            for (int h = 0; h < kH; ++h) s[h] = fma2(q2[h], s[h], xv);
        }
#pragma unroll
        for (int h = 0; h < kH; ++h)
            *reinterpret_cast<u64*>(&g_sf[b][c][h][d]) = s[h];

#pragma unroll
        for (int h = 0; h < kH; ++h) {
            float q = s_q[1][h];
            q2[h] = pack2(q, q);
            s[h] = 0ull;
        }
#pragma unroll
        for (int i = kChunk - 1; i >= 0; --i) {
            u64 xv = xs[i * kRowU64];                // L1 hit
#pragma unroll
            for (int h = 0; h < kH; ++h) s[h] = fma2(q2[h], s[h], xv);
        }
#pragma unroll
        for (int h = 0; h < kH; ++h)
            *reinterpret_cast<u64*>(&g_sr[b][c][h][d]) = s[h];
    }

    // ================= EARLY ARRIVE ==========================================
    __threadfence();                                  // publish aggregates
    __syncthreads();
    if (tid == 0) {
        unsigned t = atomicAdd(&g_bar, 1u);
        s_tgt = t - (t % kBlocks) + kBlocks;          // this launch's epoch end
    }

    // ---- barrier shadow: prefetch + fold weights (cold DRAM hidden) --------
    const u64* exu = reinterpret_cast<const u64*>(ex) + (d >> 1);
    const u64* reu = reinterpret_cast<const u64*>(re) + (d >> 1);
    u64 qF[kH], qR[kH], wF[kH], wR[kH];
#pragma unroll
    for (int h = 0; h < kH; ++h) {
        float aF = s_a[0][h], aR = s_a[1][h];
        qF[h] = pack2(s_q[0][h], s_q[0][h]);
        qR[h] = pack2(s_q[1][h], s_q[1][h]);
        wF[h] = mul2(mul2(exu[h * kRowU64], reu[h * kRowU64]),
                     pack2(aF, aF));
        wR[h] = mul2(mul2(exu[(kH + h) * kRowU64], reu[(kH + h) * kRowU64]),
                     pack2(aR, aR));
    }

    // ================= WAIT ===================================================
    __syncthreads();                                  // s_tgt visible
    if (tid == 0) {
        volatile unsigned* p = &g_bar;
        while ((int)(*p - s_tgt) < 0) { }
    }
    __syncthreads();

    const int dh = d >> 1;
    const u64* bsf = reinterpret_cast<const u64*>(g_sf) +
                     (size_t)b * kNChunk * kH * kRowU64 + dh;
    const u64* bsr = reinterpret_cast<const u64*>(g_sr) +
                     (size_t)b * kNChunk * kH * kRowU64 + dh;

    u64* od = reinterpret_cast<u64*>(
        out + ((size_t)b * kL + (size_t)c * kChunk) * kD + dt * kCols) + tid;

    // ================= forward: lookback + seeded rescan -> acc =============
    {
        const int Wf = min(s_W[0], c);
        u64 u[kH];
        float wk[kH];
#pragma unroll
        for (int h = 0; h < kH; ++h) { u[h] = 0ull; wk[h] = 1.0f; }
        for (int k = 0; k < Wf; ++k) {
            const u64* row = bsf + (size_t)(c - 1 - k) * kH * kRowU64;
#pragma unroll
            for (int h = 0; h < kH; ++h) {
                u[h] = fma2(pack2(wk[h], wk[h]), row[h * kRowU64], u[h]);
                wk[h] *= s_qc[0][h];
            }
        }
#pragma unroll
        for (int i = 0; i < kChunk; ++i) {
            u64 xv = xs[i * kRowU64];                 // L1 hit
            u64 fs = 0ull;
#pragma unroll
            for (int h = 0; h < kH; ++h) {
                u[h] = fma2(qF[h], u[h], xv);
                fs   = fma2(wF[h], u[h], fs);
            }
            acc[i * kThreads + tid] = fs;
        }
    }

    // ================= reverse: lookback + seeded rescan + store ============
    {
        const int Wr = min(s_W[1], kNChunk - 1 - c);
        u64 u[kH];
        float wk[kH];
#pragma unroll
        for (int h = 0; h < kH; ++h) { u[h] = 0ull; wk[h] = 1.0f; }
        for (int k = 0; k < Wr; ++k) {
            const u64* row = bsr + (size_t)(c + 1 + k) * kH * kRowU64;
#pragma unroll
            for (int h = 0; h < kH; ++h) {
                u[h] = fma2(pack2(wk[h], wk[h]), row[h * kRowU64], u[h]);
                wk[h] *= s_qc[1][h];
            }
        }
#pragma unroll
        for (int i = kChunk - 1; i >= 0; --i) {
            u64 xv = xs[i * kRowU64];                 // L1 hit
            u64 rs = 0ull;
#pragma unroll
            for (int h = 0; h < kH; ++h) {
                u[h] = fma2(qR[h], u[h], xv);
                rs   = fma2(wR[h], u[h], rs);
            }
            store_cs(od + i * kRowU64,
                     add2(acc[i * kThreads + tid], rs));  // out written once
        }
    }
}

// ---------------------------------------------------------------------------
extern "C" void kernel_launch(void* const* d_in, const int* in_sizes, int n_in,
                              void* d_out, int out_size)
{
    const float* x   = (const float*)d_in[0];
    const float* ex  = (const float*)d_in[1];
    const float* re  = (const float*)d_in[2];
    const float* al  = (const float*)d_in[3];
    const float* da  = (const float*)d_in[4];
    const float* ral = (const float*)d_in[5];
    const float* rda = (const float*)d_in[6];
    float* out = (float*)d_out;

    ema_fused<<<kBlocks, kThreads>>>(x, ex, re, al, da, ral, rda, out);
}